// round 9
// baseline (speedup 1.0000x reference)
#include <cuda_runtime.h>
#include <math.h>

#define D 128
#define P 17
#define HF 56
#define WF 100
#define BMAX 2
#define NMAX 40960
#define FULLMASK 0xffffffffu

// ---------------- device scratch ----------------
__device__ __align__(16) float g_img[BMAX * HF * WF * D];  // NHWC
__device__ __align__(16) float g_kWT[D * D];
__device__ __align__(16) float g_M[D * D];    // qW @ kW^T
__device__ __align__(16) float g_W2[D * D];   // vW @ outW
__device__ float g_mb[D];
__device__ float g_u[D];
__device__ float g_vbo[D];
__device__ float g_c0;

// inter-kernel pipeline scratch
__device__ __align__(16) float g_qk[(size_t)NMAX * D];
__device__ float g_qdk[NMAX];
__device__ float g_gx[NMAX * P];
__device__ float g_gy[NMAX * P];
__device__ unsigned g_vmA[NMAX];
__device__ __align__(16) float g_sagg[(size_t)NMAX * D];
__device__ float g_sn[NMAX];

__constant__ float2 c_base[P] = {
    {-1.f,-1.f},{-1.f,0.f},{-1.f,1.f},{0.f,-1.f},{0.f,0.f},{0.f,1.f},
    {1.f,-1.f},{1.f,0.f},{1.f,1.f},{-3.f,-3.f},{-3.f,0.f},{-3.f,3.f},
    {0.f,-3.f},{0.f,3.f},{3.f,-3.f},{3.f,0.f},{3.f,3.f}
};

__device__ __forceinline__ float wsum(float v) {
    #pragma unroll
    for (int o = 16; o; o >>= 1) v += __shfl_xor_sync(FULLMASK, v, o);
    return v;
}

// ---------------- prep: tiled NCHW->NHWC transpose ----------------
__global__ void prep_img_t(const float* __restrict__ img) {
    __shared__ float tile[32][33];
    int by = blockIdx.z;             // b*HF + y
    int b = by / HF, y = by % HF;
    int x0 = blockIdx.x * 32, c0 = blockIdx.y * 32;
    int tx = threadIdx.x, ty = threadIdx.y;   // 32 x 8
    #pragma unroll
    for (int i = ty; i < 32; i += 8) {
        int c = c0 + i, x = x0 + tx;
        if (x < WF) tile[i][tx] = img[((size_t)(b * D + c) * HF + y) * WF + x];
    }
    __syncthreads();
    #pragma unroll
    for (int i = ty; i < 32; i += 8) {
        int x = x0 + i, c = c0 + tx;
        if (x < WF) g_img[((size_t)(b * HF + y) * WF + x) * D + c] = tile[tx][i];
    }
}

__global__ void prep_kwt(const float* __restrict__ kW) {
    int t = blockIdx.x * blockDim.x + threadIdx.x;
    if (t >= D * D) return;
    int j = t & (D - 1);
    int e = t >> 7;
    g_kWT[t] = kW[j * D + e];
}

// merged small preps: blocks 0..127 -> M rows, 128..255 -> W2 rows, 256 -> vectors
__global__ void prep_rest(const float* __restrict__ qW, const float* __restrict__ kW,
                          const float* __restrict__ qb, const float* __restrict__ kb,
                          const float* __restrict__ vW, const float* __restrict__ vb,
                          const float* __restrict__ outW) {
    int bid = blockIdx.x;
    int j = threadIdx.x;
    if (bid < D) {                       // M row a = bid
        int a = bid;
        __shared__ float sq[D];
        sq[j] = qW[a * D + j];
        __syncthreads();
        float acc = 0.f;
        #pragma unroll 32
        for (int e = 0; e < D; e++) acc = fmaf(sq[e], g_kWT[e * D + j], acc);
        g_M[a * D + j] = acc;
    } else if (bid < 2 * D) {            // W2 row c = bid-128
        int c = bid - D;
        __shared__ float sv[D];
        sv[j] = vW[c * D + j];
        __syncthreads();
        float acc = 0.f;
        #pragma unroll 32
        for (int e = 0; e < D; e++) acc = fmaf(sv[e], outW[e * D + j], acc);
        g_W2[c * D + j] = acc;
    } else {                             // vectors
        float mb = 0.f, u = 0.f, vo = 0.f;
        #pragma unroll 32
        for (int e = 0; e < D; e++) {
            mb = fmaf(qb[e], kW[j * D + e], mb);
            u  = fmaf(qW[j * D + e], kb[e], u);
            vo = fmaf(vb[e], outW[e * D + j], vo);
        }
        g_mb[j] = mb; g_u[j] = u; g_vbo[j] = vo;
        if (j == 0) {
            float c = 0.f;
            #pragma unroll 32
            for (int e = 0; e < D; e++) c = fmaf(qb[e], kb[e], c);
            g_c0 = c;
        }
    }
}

// ================= kernel A: qk GEMV + offsets + projection + 2 stats ========
// 8 voxels per warp, 4 warps per CTA, no smem (x read via warp-broadcast LDG).
__global__ void __launch_bounds__(128)
k_qko(const float* __restrict__ x, const int* __restrict__ idxs,
      const float* __restrict__ voxel_size, const float* __restrict__ pc_range,
      const float* __restrict__ trans,
      const float* __restrict__ offW, const float* __restrict__ offb,
      const int* __restrict__ Himg, const int* __restrict__ Wimg,
      float* __restrict__ out, int N) {
    const int warp = threadIdx.x >> 5;
    const int lane = threadIdx.x & 31;
    const int n0 = (blockIdx.x * 4 + warp) * 8;
    if (n0 >= N) return;

    int nv[8];
    #pragma unroll
    for (int v = 0; v < 8; v++) { int n = n0 + v; nv[v] = (n < N) ? n : (N - 1); }

    // ---- qdk = x.u + c0 ----
    {
        float4 u4 = *(const float4*)&g_u[4 * lane];
        float c0v = g_c0;
        #pragma unroll
        for (int v = 0; v < 8; v++) {
            float4 xr = *(const float4*)&x[(size_t)nv[v] * D + 4 * lane];
            float qd = wsum(xr.x*u4.x + xr.y*u4.y + xr.z*u4.z + xr.w*u4.w) + c0v;
            if (lane == 0 && n0 + v < N) g_qdk[n0 + v] = qd;
        }
    }

    // ---- fused GEMVs: qk (all lanes, 4 ch each) + offsets (lanes<17) ----
    float4 acc[8];
    float ax[8], ay[8];
    #pragma unroll
    for (int v = 0; v < 8; v++) {
        acc[v] = make_float4(0.f,0.f,0.f,0.f);
        ax[v] = 0.f; ay[v] = 0.f;
    }
    const bool ol = lane < P;
    const float2* ow2 = (const float2*)offW;
    #pragma unroll 2
    for (int a2 = 0; a2 < D / 2; a2++) {
        float4 m0 = *(const float4*)&g_M[(2 * a2) * D + 4 * lane];
        float4 m1 = *(const float4*)&g_M[(2 * a2 + 1) * D + 4 * lane];
        float2 w0 = ol ? ow2[(2 * a2) * P + lane]     : make_float2(0.f, 0.f);
        float2 w1 = ol ? ow2[(2 * a2 + 1) * P + lane] : make_float2(0.f, 0.f);
        #pragma unroll
        for (int v = 0; v < 8; v++) {
            float2 xa = *(const float2*)&x[(size_t)nv[v] * D + 2 * a2];  // broadcast
            acc[v].x = fmaf(xa.x, m0.x, acc[v].x); acc[v].y = fmaf(xa.x, m0.y, acc[v].y);
            acc[v].z = fmaf(xa.x, m0.z, acc[v].z); acc[v].w = fmaf(xa.x, m0.w, acc[v].w);
            acc[v].x = fmaf(xa.y, m1.x, acc[v].x); acc[v].y = fmaf(xa.y, m1.y, acc[v].y);
            acc[v].z = fmaf(xa.y, m1.z, acc[v].z); acc[v].w = fmaf(xa.y, m1.w, acc[v].w);
            ax[v] = fmaf(xa.x, w0.x, ax[v]); ay[v] = fmaf(xa.x, w0.y, ay[v]);
            ax[v] = fmaf(xa.y, w1.x, ax[v]); ay[v] = fmaf(xa.y, w1.y, ay[v]);
        }
    }
    {
        float4 mb4 = *(const float4*)&g_mb[4 * lane];
        #pragma unroll
        for (int v = 0; v < 8; v++) {
            int n = n0 + v;
            if (n < N) {
                float4 o = make_float4(acc[v].x + mb4.x, acc[v].y + mb4.y,
                                       acc[v].z + mb4.z, acc[v].w + mb4.w);
                *(float4*)&g_qk[(size_t)n * D + 4 * lane] = o;
            }
        }
    }

    // ---- projection + learned offsets + vm + 2 stats ----
    const float du = 2.0f / (float)(WF - 1);
    const float dv = 2.0f / (float)(HF - 1);
    float cv0 = voxel_size[0] * 8.0f, cv1 = voxel_size[1] * 8.0f, cv2 = voxel_size[2] * 8.0f;
    float pr0 = pc_range[0], pr1 = pc_range[1], pr2 = pc_range[2];
    float wsc = (float)WF / (float)Wimg[0];
    float hsc = (float)HF / (float)Himg[0];
    float2 ob = ol ? ((const float2*)offb)[lane] : make_float2(0.f, 0.f);
    float bx = ol ? c_base[lane].x : 0.f;
    float by = ol ? c_base[lane].y : 0.f;
    float oscale = 1.5f * fmaxf(sqrtf(du * du + dv * dv), 1e-6f);

    #pragma unroll
    for (int v = 0; v < 8; v++) {
        int4 vidx = *(const int4*)&idxs[(size_t)nv[v] * 4];
        float ph0 = (float)vidx.w * cv0 + pr0 + cv0 * 0.5f;
        float ph1 = (float)vidx.z * cv1 + pr1 + cv1 * 0.5f;
        float ph2 = (float)vidx.y * cv2 + pr2 + cv2 * 0.5f;
        const float* T = trans + vidx.x * 12;
        float X = T[0]*ph0 + T[1]*ph1 + T[2]*ph2 + T[3];
        float Y = T[4]*ph0 + T[5]*ph1 + T[6]*ph2 + T[7];
        float Z = T[8]*ph0 + T[9]*ph1 + T[10]*ph2 + T[11];
        float depth = fmaxf(Z, 1e-5f);
        float un = 2.0f * ((X / depth * wsc) / (float)(WF - 1)) - 1.0f;
        float vn = 2.0f * ((Y / depth * hsc) / (float)(HF - 1)) - 1.0f;

        float dx = tanhf(ax[v] + ob.x) * (1.5f * du);
        float dy = tanhf(ay[v] + ob.y) * (1.5f * dv);
        float gx = un + bx * du + dx;
        float gy = vn + by * dv + dy;
        float ln = sqrtf(dx * dx + dy * dy);
        bool val = ol && (fabsf(gx) <= 1.0f) && (fabsf(gy) <= 1.0f);
        unsigned vm = __ballot_sync(FULLMASK, val);
        float lsum = wsum(ol ? ln : 0.f);

        int n = n0 + v;
        if (n < N) {
            if (ol) {
                g_gx[(size_t)n * P + lane] = gx;
                g_gy[(size_t)n * P + lane] = gy;
            }
            if (lane == 0) {
                g_vmA[n] = vm;
                size_t base = (size_t)N * D;
                out[base + n] = (float)__popc(vm) / 17.0f;
                float instab = (lsum / 17.0f) / oscale;
                out[base + N + n] = fminf(fmaxf(expf(-instab), 0.f), 1.f);
            }
        }
    }
}

// ================= kernel B: gather + online softmax (1 voxel per warp) =====
__global__ void __launch_bounds__(256)
k_attn(const int* __restrict__ idxs, float* __restrict__ out, int N) {
    const int warp = threadIdx.x >> 5;
    const int lane = threadIdx.x & 31;
    const int n = blockIdx.x * 8 + warp;
    if (n >= N) return;

    unsigned vm = g_vmA[n];
    int b = idxs[(size_t)n * 4];
    float gx = 0.f, gy = 0.f;
    if (lane < P) {
        gx = g_gx[(size_t)n * P + lane];
        gy = g_gy[(size_t)n * P + lane];
    }
    float4 qk = *(const float4*)&g_qk[(size_t)n * D + 4 * lane];
    float qdk = g_qdk[n];
    const float scale = 0.1767766953f;   // 32^-0.5
    const float* ib = g_img + (size_t)b * (HF * WF * D);

    float m_run = -3.0e38f, ssum = 0.f;
    float4 agg = make_float4(0.f,0.f,0.f,0.f);
    float myattn = 0.f;

    for (int p = 0; p < P; p++) {
        if (!((vm >> p) & 1u)) continue;           // warp-uniform
        float gxp = __shfl_sync(FULLMASK, gx, p);
        float gyp = __shfl_sync(FULLMASK, gy, p);
        float px = (gxp + 1.0f) * 0.5f * (float)(WF - 1);
        float py = (gyp + 1.0f) * 0.5f * (float)(HF - 1);
        float fx0 = floorf(px), fy0 = floorf(py);
        int ix = (int)fx0, iy = (int)fy0;
        float fx = px - fx0, fy = py - fy0;
        float4 feat = make_float4(0.f,0.f,0.f,0.f);
        #pragma unroll
        for (int t = 0; t < 4; t++) {
            int dxt = t & 1, dyt = t >> 1;
            int xc = ix + dxt, yc = iy + dyt;
            if (xc >= 0 && xc < WF && yc >= 0 && yc < HF) {
                float w = (dxt ? fx : 1.0f - fx) * (dyt ? fy : 1.0f - fy);
                float4 f = *(const float4*)&ib[((size_t)yc * WF + xc) * D + 4 * lane];
                feat.x = fmaf(w, f.x, feat.x); feat.y = fmaf(w, f.y, feat.y);
                feat.z = fmaf(w, f.z, feat.z); feat.w = fmaf(w, f.w, feat.w);
            }
        }
        float pd = feat.x*qk.x + feat.y*qk.y + feat.z*qk.z + feat.w*qk.w;
        float a = (wsum(pd) + qdk) * scale;
        float nm = fmaxf(m_run, a);
        float cc = expf(m_run - nm);
        float e  = expf(a - nm);
        ssum = ssum * cc + e;
        agg.x = agg.x * cc + e * feat.x; agg.y = agg.y * cc + e * feat.y;
        agg.z = agg.z * cc + e * feat.z; agg.w = agg.w * cc + e * feat.w;
        m_run = nm;
        if (lane == p) myattn = a;
    }

    bool anyv = (vm != 0u);
    float inv_s = anyv ? (1.0f / ssum) : 0.f;
    float4 an = make_float4(agg.x*inv_s, agg.y*inv_s, agg.z*inv_s, agg.w*inv_s);
    *(float4*)&g_sagg[(size_t)n * D + 4 * lane] = an;

    float wn = (lane < P && ((vm >> lane) & 1u)) ? expf(myattn - m_run) * inv_s : 0.f;
    float pe = fmaxf(wn, 1e-6f);
    float ent = wsum(lane < P ? (-pe * logf(pe)) : 0.f);
    if (lane == 0) {
        g_sn[n] = anyv ? 1.0f : 0.f;
        float focus = 1.0f - ent / logf(17.0f);
        out[(size_t)N * D + 2 * (size_t)N + n] = fminf(fmaxf(focus, 0.f), 1.f);
    }
}

// ================= kernel C: out = sagg @ W2 + s_n*vbo + outb ===============
__global__ void __launch_bounds__(128)
k_out(const float* __restrict__ outb_, float* __restrict__ out, int N) {
    const int warp = threadIdx.x >> 5;
    const int lane = threadIdx.x & 31;
    const int n0 = (blockIdx.x * 4 + warp) * 8;
    if (n0 >= N) return;

    int nv[8];
    float sn[8];
    #pragma unroll
    for (int v = 0; v < 8; v++) {
        int n = n0 + v; nv[v] = (n < N) ? n : (N - 1);
        sn[v] = g_sn[nv[v]];
    }

    float4 acc[8];
    #pragma unroll
    for (int v = 0; v < 8; v++) acc[v] = make_float4(0.f,0.f,0.f,0.f);

    #pragma unroll 2
    for (int c2 = 0; c2 < D / 2; c2++) {
        float4 m0 = *(const float4*)&g_W2[(2 * c2) * D + 4 * lane];
        float4 m1 = *(const float4*)&g_W2[(2 * c2 + 1) * D + 4 * lane];
        #pragma unroll
        for (int v = 0; v < 8; v++) {
            float2 sa = *(const float2*)&g_sagg[(size_t)nv[v] * D + 2 * c2];  // broadcast
            acc[v].x = fmaf(sa.x, m0.x, acc[v].x); acc[v].y = fmaf(sa.x, m0.y, acc[v].y);
            acc[v].z = fmaf(sa.x, m0.z, acc[v].z); acc[v].w = fmaf(sa.x, m0.w, acc[v].w);
            acc[v].x = fmaf(sa.y, m1.x, acc[v].x); acc[v].y = fmaf(sa.y, m1.y, acc[v].y);
            acc[v].z = fmaf(sa.y, m1.z, acc[v].z); acc[v].w = fmaf(sa.y, m1.w, acc[v].w);
        }
    }

    float4 vbo = *(const float4*)&g_vbo[4 * lane];
    float4 ob4 = *(const float4*)&outb_[4 * lane];
    #pragma unroll
    for (int v = 0; v < 8; v++) {
        int n = n0 + v;
        if (n < N) {
            float4 o;
            o.x = acc[v].x + fmaf(sn[v], vbo.x, ob4.x);
            o.y = acc[v].y + fmaf(sn[v], vbo.y, ob4.y);
            o.z = acc[v].z + fmaf(sn[v], vbo.z, ob4.z);
            o.w = acc[v].w + fmaf(sn[v], vbo.w, ob4.w);
            *(float4*)&out[(size_t)n * D + 4 * lane] = o;
        }
    }
}

// ---------------- launch ----------------
extern "C" void kernel_launch(void* const* d_in, const int* in_sizes, int n_in,
                              void* d_out, int out_size) {
    const float* x_lidar = (const float*)d_in[0];
    const int*   indices = (const int*)d_in[1];
    const float* img     = (const float*)d_in[2];
    const float* vsize   = (const float*)d_in[3];
    const float* pcr     = (const float*)d_in[4];
    const float* trans   = (const float*)d_in[5];
    const float* offW    = (const float*)d_in[6];
    const float* offb    = (const float*)d_in[7];
    const float* qW      = (const float*)d_in[8];
    const float* qb      = (const float*)d_in[9];
    const float* kW      = (const float*)d_in[10];
    const float* kb      = (const float*)d_in[11];
    const float* vW      = (const float*)d_in[12];
    const float* vb      = (const float*)d_in[13];
    const float* outW    = (const float*)d_in[14];
    const float* outb    = (const float*)d_in[15];
    const int*   Himg    = (const int*)d_in[16];
    const int*   Wimg    = (const int*)d_in[17];

    int N = in_sizes[0] / D;
    int B = in_sizes[5] / 12;
    if (B > BMAX) B = BMAX;

    dim3 tgrid((WF + 31) / 32, D / 32, B * HF);
    prep_img_t<<<tgrid, dim3(32, 8)>>>(img);
    prep_kwt<<<(D * D + 255) / 256, 256>>>(kW);
    prep_rest<<<2 * D + 1, D>>>(qW, kW, qb, kb, vW, vb, outW);

    int blocksA = (N + 31) / 32;
    k_qko<<<blocksA, 128>>>(x_lidar, indices, vsize, pcr, trans, offW, offb,
                            Himg, Wimg, (float*)d_out, N);
    int blocksB = (N + 7) / 8;
    k_attn<<<blocksB, 256>>>(indices, (float*)d_out, N);
    int blocksC = (N + 31) / 32;
    k_out<<<blocksC, 128>>>(outb, (float*)d_out, N);
}